// round 3
// baseline (speedup 1.0000x reference)
#include <cuda_runtime.h>

#define BB   32
#define FEAT 512
#define TT   1024
#define LLAT 288
#define TCC  512
#define GG   4
#define KK   1024
#define DD   144

typedef unsigned long long u64;

// scratch (device globals: allocation-free rule)
__device__ __align__(256) float g_z[BB * TT * LLAT];   // z stored [b][t][l]
__device__ __align__(256) float g_e2[GG * KK];         // ||e||^2 per codeword
__device__ __align__(256) int   g_idx[BB * TCC * GG];  // argmin indices [b][tc][g]

__device__ __forceinline__ void fma2(u64 &c, u64 a, u64 b) {
    asm("fma.rn.f32x2 %0, %1, %2, %0;" : "+l"(c) : "l"(a), "l"(b));
}
__device__ __forceinline__ u64 dup2(float x) {
    u64 r; asm("mov.b64 %0, {%1, %1};" : "=l"(r) : "f"(x)); return r;
}
__device__ __forceinline__ float2 unpack2(u64 v) {
    float2 f; asm("mov.b64 {%0, %1}, %2;" : "=f"(f.x), "=f"(f.y) : "l"(v)); return f;
}

// ---------------------------------------------------------------------------
// Kernel 1: codeword squared norms  e2[g,k] = sum_d cb[g,k,d]^2
// ---------------------------------------------------------------------------
__global__ void e2_kernel(const float* __restrict__ cb) {
    int row  = blockIdx.x * 8 + (threadIdx.x >> 5);   // 4096 rows total
    int lane = threadIdx.x & 31;
    const float* p = cb + (size_t)row * DD;
    float s = 0.f;
    #pragma unroll
    for (int d0 = 0; d0 < DD; d0 += 32) {
        int d = d0 + lane;
        if (d < DD) { float v = p[d]; s += v * v; }
    }
    #pragma unroll
    for (int o = 16; o; o >>= 1) s += __shfl_xor_sync(0xffffffffu, s, o);
    if (lane == 0) g_e2[row] = s;
}

// ---------------------------------------------------------------------------
// Kernel 2: projection  z[b][t][l] = sum_f x[b][f][t] * w1[l][f]
// Block tile: 128 t x 96 l, K-tile 16.  f32x2 pairs along l.
// x operand pre-duplicated in SMEM so inner loop has no packing movs.
// ---------------------------------------------------------------------------
__global__ __launch_bounds__(256) void proj_kernel(
        const float* __restrict__ x, const float* __restrict__ w1) {
    __shared__ u64 xs2[16][128];                 // dup'd x tile [k][t]
    __shared__ __align__(8) float ws[16][98];    // w1 tile [k][l], pad 2

    const int b  = blockIdx.z;
    const int t0 = blockIdx.x * 128;
    const int l0 = blockIdx.y * 96;
    const int tid = threadIdx.x;
    const int it = tid & 15;        // t sub-index  (t = i*16 + it)
    const int jl = tid >> 4;        // l group: l = jl*6 + 2*j + {0,1}

    u64 c[8][3];
    #pragma unroll
    for (int i = 0; i < 8; i++)
        #pragma unroll
        for (int j = 0; j < 3; j++) c[i][j] = 0ull;

    const float* xb = x + (size_t)b * FEAT * TT + t0;

    for (int kt = 0; kt < FEAT; kt += 16) {
        #pragma unroll
        for (int r = 0; r < 8; r++) {            // 16x128 x-tile, coalesced
            int e = r * 256 + tid;
            int k = e >> 7, t = e & 127;
            xs2[k][t] = dup2(xb[(size_t)(kt + k) * TT + t]);
        }
        #pragma unroll
        for (int r = 0; r < 6; r++) {            // 16x96 w1-tile
            int e = r * 256 + tid;
            int l = e >> 4, k = e & 15;
            ws[k][l] = w1[(size_t)(l0 + l) * FEAT + kt + k];
        }
        __syncthreads();
        #pragma unroll
        for (int k = 0; k < 16; k++) {
            u64 av[8], bv[3];
            #pragma unroll
            for (int i = 0; i < 8; i++) av[i] = xs2[k][i * 16 + it];
            #pragma unroll
            for (int j = 0; j < 3; j++)
                bv[j] = *(const u64*)&ws[k][jl * 6 + 2 * j];
            #pragma unroll
            for (int i = 0; i < 8; i++)
                #pragma unroll
                for (int j = 0; j < 3; j++) fma2(c[i][j], av[i], bv[j]);
        }
        __syncthreads();
    }

    float* zb = g_z + (size_t)b * TT * LLAT;
    #pragma unroll
    for (int i = 0; i < 8; i++) {
        int t = t0 + i * 16 + it;
        #pragma unroll
        for (int j = 0; j < 3; j++)
            *(u64*)&zb[(size_t)t * LLAT + l0 + jl * 6 + 2 * j] = c[i][j];
    }
}

// ---------------------------------------------------------------------------
// Kernel 3: distance + argmin per (b,tc,g).
// Block: 64 rows x full K=1024 (8 col-tiles of 128) for one group.
// v tile kept resident (dup'd, transposed) in dynamic SMEM; cb streamed.
// score = e2[k] - 2*<v,e_k>  (v^2 constant per row -> dropped).
// ---------------------------------------------------------------------------
#define DIST_SMEM (144*65*8 + 16*130*4 + 1024*4 + 64*16*4 + 64*16*4)

__global__ __launch_bounds__(256) void dist_kernel(const float* __restrict__ cb) {
    extern __shared__ __align__(16) char smem[];
    u64*   vs2  = (u64*)smem;                      // [144][65] dup'd v, [d][r]
    float* cbs  = (float*)(smem + 144 * 65 * 8);   // [16][130] cb tile, [d][k]
    float* e2s  = cbs + 16 * 130;                  // [1024]
    float* rmin = e2s + 1024;                      // [64][16]
    int*   rkid = (int*)(rmin + 64 * 16);          // [64][16]

    const int g  = blockIdx.y;
    const int r0 = blockIdx.x * 64;
    const int tid = threadIdx.x;
    const int ir = tid & 15;      // row sub-index (r = i*16 + ir)
    const int kg = tid >> 4;      // k pair group: pair p = j*16 + kg

    for (int e = tid; e < KK; e += 256) e2s[e] = g_e2[g * KK + e];

    const int lbase = (g & 1) * DD;
    const int pofs  = g >> 1;
    for (int e = tid; e < 64 * DD; e += 256) {
        int r = e / DD, d = e - r * DD;
        int rg = r0 + r;
        int b = rg >> 9, tc = rg & 511;
        float v = g_z[(size_t)(b * TT + 2 * tc + pofs) * LLAT + lbase + d];
        vs2[d * 65 + r] = dup2(v);
    }
    __syncthreads();

    float minv[4]; int mink[4];
    #pragma unroll
    for (int i = 0; i < 4; i++) { minv[i] = 3.4e38f; mink[i] = 0; }

    const float* cbg = cb + (size_t)g * KK * DD;

    for (int kt = 0; kt < KK; kt += 128) {
        u64 c[4][4];
        #pragma unroll
        for (int i = 0; i < 4; i++)
            #pragma unroll
            for (int j = 0; j < 4; j++) c[i][j] = 0ull;

        for (int dt = 0; dt < DD; dt += 16) {
            #pragma unroll
            for (int r = 0; r < 8; r++) {        // 128k x 16d tile, coalesced on d
                int e = r * 256 + tid;
                int k = e >> 4, d = e & 15;
                cbs[d * 130 + k] = cbg[(size_t)(kt + k) * DD + dt + d];
            }
            __syncthreads();
            #pragma unroll
            for (int dd = 0; dd < 16; dd++) {
                u64 av[4], bv[4];
                #pragma unroll
                for (int i = 0; i < 4; i++)
                    av[i] = vs2[(dt + dd) * 65 + i * 16 + ir];
                #pragma unroll
                for (int j = 0; j < 4; j++)
                    bv[j] = *(const u64*)&cbs[dd * 130 + 2 * (j * 16 + kg)];
                #pragma unroll
                for (int i = 0; i < 4; i++)
                    #pragma unroll
                    for (int j = 0; j < 4; j++) fma2(c[i][j], av[i], bv[j]);
            }
            __syncthreads();
        }
        // fold this col-tile into the running argmin (ascending k within thread)
        #pragma unroll
        for (int j = 0; j < 4; j++) {
            int ke = kt + 2 * (j * 16 + kg);
            float e0 = e2s[ke], e1 = e2s[ke + 1];
            #pragma unroll
            for (int i = 0; i < 4; i++) {
                float2 f = unpack2(c[i][j]);
                float s0 = e0 - 2.f * f.x;
                float s1 = e1 - 2.f * f.y;
                if (s0 < minv[i]) { minv[i] = s0; mink[i] = ke; }
                if (s1 < minv[i]) { minv[i] = s1; mink[i] = ke + 1; }
            }
        }
    }

    #pragma unroll
    for (int i = 0; i < 4; i++) {
        int r = i * 16 + ir;
        rmin[r * 16 + kg] = minv[i];
        rkid[r * 16 + kg] = mink[i];
    }
    __syncthreads();
    if (tid < 64) {   // reduce 16 partials per row; tie-break to lowest k
        float bvv = rmin[tid * 16]; int bk = rkid[tid * 16];
        #pragma unroll
        for (int q = 1; q < 16; q++) {
            float v = rmin[tid * 16 + q]; int k = rkid[tid * 16 + q];
            if (v < bvv || (v == bvv && k < bk)) { bvv = v; bk = k; }
        }
        g_idx[(r0 + tid) * GG + g] = bk;
    }
}

// ---------------------------------------------------------------------------
// Kernel 4: reconstruction  out[b][f][t] = sum_l w2[f][l] * q[b][t][l]
// q gathered directly from codebooks via g_idx (no materialized q buffer).
// Block tile: 64 f x 128 t, K-tile 16 over l.  f32x2 pairs along t.
// ---------------------------------------------------------------------------
__global__ __launch_bounds__(256) void recon_kernel(
        const float* __restrict__ w2, const float* __restrict__ cb,
        float* __restrict__ out) {
    __shared__ u64 as2[16][65];                  // dup'd w2 tile [l][f], pad 1
    __shared__ __align__(8) float qs[16][130];   // gathered q tile [l][t], pad 2

    const int b  = blockIdx.z;
    const int t0 = blockIdx.x * 128;
    const int f0 = blockIdx.y * 64;
    const int tid = threadIdx.x;
    const int ir = tid & 15;      // f sub-index (f = i*16 + ir)
    const int kg = tid >> 4;      // t pair group: pair p = j*16 + kg

    u64 c[4][4];
    #pragma unroll
    for (int i = 0; i < 4; i++)
        #pragma unroll
        for (int j = 0; j < 4; j++) c[i][j] = 0ull;

    const int* idxb = g_idx + b * TCC * GG;

    for (int lt = 0; lt < LLAT; lt += 16) {      // 18 K-tiles; aligned to 144 split
        int lhi = (lt >= DD) ? 1 : 0;
        int d0  = lt - lhi * DD;
        #pragma unroll
        for (int r = 0; r < 4; r++) {            // 64f x 16l w2-tile
            int e = r * 256 + tid;
            int l = e & 15, f = e >> 4;
            as2[l][f] = dup2(w2[(size_t)(f0 + f) * LLAT + lt + l]);
        }
        #pragma unroll
        for (int r = 0; r < 8; r++) {            // 16l x 128t gathered q-tile
            int e = r * 256 + tid;
            int l = e & 15, t = e >> 4;
            int tt = t0 + t;
            int gq = ((tt & 1) << 1) | lhi;      // group = 2*frame_parity + l/144
            int ck = idxb[(tt >> 1) * GG + gq];
            qs[l][t] = cb[((size_t)(gq * KK + ck)) * DD + d0 + l];
        }
        __syncthreads();
        #pragma unroll
        for (int l = 0; l < 16; l++) {
            u64 av[4], bv[4];
            #pragma unroll
            for (int i = 0; i < 4; i++) av[i] = as2[l][i * 16 + ir];
            #pragma unroll
            for (int j = 0; j < 4; j++)
                bv[j] = *(const u64*)&qs[l][2 * (j * 16 + kg)];
            #pragma unroll
            for (int i = 0; i < 4; i++)
                #pragma unroll
                for (int j = 0; j < 4; j++) fma2(c[i][j], av[i], bv[j]);
        }
        __syncthreads();
    }

    float* ob = out + ((size_t)b * FEAT + f0) * TT + t0;
    #pragma unroll
    for (int i = 0; i < 4; i++)
        #pragma unroll
        for (int j = 0; j < 4; j++)
            *(u64*)&ob[(size_t)(i * 16 + ir) * TT + 2 * (j * 16 + kg)] = c[i][j];
}

// ---------------------------------------------------------------------------
extern "C" void kernel_launch(void* const* d_in, const int* in_sizes, int n_in,
                              void* d_out, int out_size) {
    const float* x  = (const float*)d_in[0];
    const float* w1 = (const float*)d_in[1];
    const float* w2 = (const float*)d_in[2];
    const float* cb = (const float*)d_in[3];
    float* out = (float*)d_out;

    cudaFuncSetAttribute(dist_kernel,
                         cudaFuncAttributeMaxDynamicSharedMemorySize, DIST_SMEM);

    e2_kernel  <<<GG * KK / 8, 256>>>(cb);
    proj_kernel<<<dim3(TT / 128, LLAT / 96, BB), 256>>>(x, w1);
    dist_kernel<<<dim3(BB * TCC / 64, GG), 256, DIST_SMEM>>>(cb);
    recon_kernel<<<dim3(TT / 128, FEAT / 64, BB), 256>>>(w2, cb, out);
}

// round 4
// speedup vs baseline: 1.0858x; 1.0858x over previous
#include <cuda_runtime.h>

#define BB   32
#define FEAT 512
#define TT   1024
#define LLAT 288
#define TCC  512
#define GG   4
#define KK   1024
#define DD   144

typedef unsigned long long u64;

// scratch (device globals: allocation-free rule)
__device__ __align__(256) float g_z[BB * TT * LLAT];   // z stored [b][t][l]
__device__ __align__(256) float g_e2[GG * KK];         // ||e||^2 per codeword
__device__ __align__(256) int   g_idx[BB * TCC * GG];  // argmin indices [b][tc][g]

__device__ __forceinline__ void fma2(u64 &c, u64 a, u64 b) {
    asm("fma.rn.f32x2 %0, %1, %2, %0;" : "+l"(c) : "l"(a), "l"(b));
}
__device__ __forceinline__ u64 dup2(float x) {
    u64 r; asm("mov.b64 %0, {%1, %1};" : "=l"(r) : "f"(x)); return r;
}
__device__ __forceinline__ float2 unpack2(u64 v) {
    float2 f; asm("mov.b64 {%0, %1}, %2;" : "=f"(f.x), "=f"(f.y) : "l"(v)); return f;
}

// ---------------------------------------------------------------------------
// Kernel 1: codeword squared norms  e2[g,k] = sum_d cb[g,k,d]^2
// ---------------------------------------------------------------------------
__global__ void e2_kernel(const float* __restrict__ cb) {
    int row  = blockIdx.x * 8 + (threadIdx.x >> 5);
    int lane = threadIdx.x & 31;
    const float* p = cb + (size_t)row * DD;
    float s = 0.f;
    #pragma unroll
    for (int d0 = 0; d0 < DD; d0 += 32) {
        int d = d0 + lane;
        if (d < DD) { float v = p[d]; s += v * v; }
    }
    #pragma unroll
    for (int o = 16; o; o >>= 1) s += __shfl_xor_sync(0xffffffffu, s, o);
    if (lane == 0) g_e2[row] = s;
}

// ---------------------------------------------------------------------------
// Kernel 2: projection  z[b][t][l] = sum_f x[b][f][t] * w1[l][f]
// Tile: 128 t-rows x 288 l-cols (full L), K-tile 16.  I=8 (dup'd x), J=9.
// ---------------------------------------------------------------------------
__global__ __launch_bounds__(256, 1) void proj_kernel(
        const float* __restrict__ x, const float* __restrict__ w1) {
    __shared__ u64 xs2[16 * 129];                 // dup'd x tile [k][t]
    __shared__ __align__(8) float ws[16 * 290];   // w1 tile [k][l]

    const int b  = blockIdx.z;
    const int t0 = blockIdx.x * 128;
    const int tid = threadIdx.x;
    const int ir = tid & 15;        // t = i*16 + ir
    const int kg = tid >> 4;        // l pair p = j*16 + kg

    u64 c[8][9];
    #pragma unroll
    for (int i = 0; i < 8; i++)
        #pragma unroll
        for (int j = 0; j < 9; j++) c[i][j] = 0ull;

    const float* xb = x + (size_t)b * FEAT * TT + t0;

    for (int kt = 0; kt < FEAT; kt += 16) {
        #pragma unroll
        for (int r = 0; r < 8; r++) {            // 16k x 128t x-tile, coalesced
            int e = r * 256 + tid;
            int k = e >> 7, t = e & 127;
            xs2[k * 129 + t] = dup2(xb[(size_t)(kt + k) * TT + t]);
        }
        #pragma unroll
        for (int r = 0; r < 18; r++) {           // 16k x 288l w1-tile
            int e = r * 256 + tid;
            int l = e >> 4, k = e & 15;
            ws[k * 290 + l] = w1[(size_t)l * FEAT + kt + k];
        }
        __syncthreads();
        #pragma unroll
        for (int k = 0; k < 16; k++) {
            u64 av[8], bv[9];
            #pragma unroll
            for (int i = 0; i < 8; i++) av[i] = xs2[k * 129 + i * 16 + ir];
            #pragma unroll
            for (int j = 0; j < 9; j++)
                bv[j] = *(const u64*)&ws[k * 290 + 2 * (j * 16 + kg)];
            #pragma unroll
            for (int i = 0; i < 8; i++)
                #pragma unroll
                for (int j = 0; j < 9; j++) fma2(c[i][j], av[i], bv[j]);
        }
        __syncthreads();
    }

    float* zb = g_z + (size_t)b * TT * LLAT;
    #pragma unroll
    for (int i = 0; i < 8; i++) {
        int t = t0 + i * 16 + ir;
        #pragma unroll
        for (int j = 0; j < 9; j++)
            *(u64*)&zb[(size_t)t * LLAT + 2 * (j * 16 + kg)] = c[i][j];
    }
}

// ---------------------------------------------------------------------------
// Kernel 3: distance + argmin per (b,tc,g).
// Block: 128 rows x k-tile 256 (4 tiles cover K=1024).  I=8, J=8.
// v tile resident (dup'd) in dynamic SMEM; cb streamed (L2-hot).
// score = e2[k] - 2*<v,e_k>   (||v||^2 row-constant -> dropped).
// ---------------------------------------------------------------------------
#define DIST_SMEM (144*129*8 + 16*258*4 + 1024*4 + 128*16*4 + 128*16*4)

__global__ __launch_bounds__(256, 1) void dist_kernel(const float* __restrict__ cb) {
    extern __shared__ __align__(16) char smem[];
    u64*   vs2  = (u64*)smem;                        // [144][129] dup'd v [d][r]
    float* cbs  = (float*)(smem + 144 * 129 * 8);    // [16][258] cb tile [d][k]
    float* e2s  = cbs + 16 * 258;                    // [1024]
    float* rmin = e2s + 1024;                        // [128][16]
    int*   rkid = (int*)(rmin + 128 * 16);           // [128][16]

    const int g  = blockIdx.y;
    const int r0 = blockIdx.x * 128;
    const int tid = threadIdx.x;
    const int ir = tid & 15;      // row r = i*16 + ir
    const int kg = tid >> 4;      // k pair p = j*16 + kg

    for (int e = tid; e < KK; e += 256) e2s[e] = g_e2[g * KK + e];

    const int lbase = (g & 1) * DD;
    const int pofs  = g >> 1;
    for (int e = tid; e < 128 * DD; e += 256) {
        int r = e / DD, d = e - r * DD;
        int rg = r0 + r;
        int b = rg >> 9, tc = rg & 511;
        float v = g_z[(size_t)(b * TT + 2 * tc + pofs) * LLAT + lbase + d];
        vs2[d * 129 + r] = dup2(v);
    }
    __syncthreads();

    float minv[8]; int mink[8];
    #pragma unroll
    for (int i = 0; i < 8; i++) { minv[i] = 3.4e38f; mink[i] = 0; }

    const float* cbg = cb + (size_t)g * KK * DD;

    for (int kt = 0; kt < KK; kt += 256) {
        u64 c[8][8];
        #pragma unroll
        for (int i = 0; i < 8; i++)
            #pragma unroll
            for (int j = 0; j < 8; j++) c[i][j] = 0ull;

        for (int dt = 0; dt < DD; dt += 16) {
            #pragma unroll
            for (int r = 0; r < 16; r++) {       // 256k x 16d tile, coalesced on d
                int e = r * 256 + tid;
                int k = e >> 4, d = e & 15;
                cbs[d * 258 + k] = cbg[(size_t)(kt + k) * DD + dt + d];
            }
            __syncthreads();
            #pragma unroll
            for (int dd = 0; dd < 16; dd++) {
                u64 av[8], bv[8];
                #pragma unroll
                for (int i = 0; i < 8; i++)
                    av[i] = vs2[(dt + dd) * 129 + i * 16 + ir];
                #pragma unroll
                for (int j = 0; j < 8; j++)
                    bv[j] = *(const u64*)&cbs[dd * 258 + 2 * (j * 16 + kg)];
                #pragma unroll
                for (int i = 0; i < 8; i++)
                    #pragma unroll
                    for (int j = 0; j < 8; j++) fma2(c[i][j], av[i], bv[j]);
            }
            __syncthreads();
        }
        // fold this col-tile into running argmin (k ascending within thread)
        #pragma unroll
        for (int j = 0; j < 8; j++) {
            int ke = kt + 2 * (j * 16 + kg);
            float e0 = e2s[ke], e1 = e2s[ke + 1];
            #pragma unroll
            for (int i = 0; i < 8; i++) {
                float2 f = unpack2(c[i][j]);
                float s0 = e0 - 2.f * f.x;
                float s1 = e1 - 2.f * f.y;
                if (s0 < minv[i]) { minv[i] = s0; mink[i] = ke; }
                if (s1 < minv[i]) { minv[i] = s1; mink[i] = ke + 1; }
            }
        }
    }

    #pragma unroll
    for (int i = 0; i < 8; i++) {
        int r = i * 16 + ir;
        rmin[r * 16 + kg] = minv[i];
        rkid[r * 16 + kg] = mink[i];
    }
    __syncthreads();
    if (tid < 128) {  // reduce 16 partials per row; tie-break to lowest k
        float bvv = rmin[tid * 16]; int bk = rkid[tid * 16];
        #pragma unroll
        for (int q = 1; q < 16; q++) {
            float v = rmin[tid * 16 + q]; int k = rkid[tid * 16 + q];
            if (v < bvv || (v == bvv && k < bk)) { bvv = v; bk = k; }
        }
        g_idx[(r0 + tid) * GG + g] = bk;
    }
}

// ---------------------------------------------------------------------------
// Kernel 4: reconstruction  out[b][f][t] = sum_l w2[f][l] * q[b][t][l]
// q gathered from codebooks via g_idx.  Tile 128 f x 256 t, K-tile 16.
// I=8 (dup'd w2), J=8 (t pairs).
// ---------------------------------------------------------------------------
__global__ __launch_bounds__(256, 1) void recon_kernel(
        const float* __restrict__ w2, const float* __restrict__ cb,
        float* __restrict__ out) {
    __shared__ u64 as2[16 * 129];                 // dup'd w2 tile [l][f]
    __shared__ __align__(8) float qs[16 * 258];   // gathered q tile [l][t]

    const int b  = blockIdx.z;
    const int t0 = blockIdx.x * 256;
    const int f0 = blockIdx.y * 128;
    const int tid = threadIdx.x;
    const int ir = tid & 15;      // f = i*16 + ir
    const int kg = tid >> 4;      // t pair p = j*16 + kg

    u64 c[8][8];
    #pragma unroll
    for (int i = 0; i < 8; i++)
        #pragma unroll
        for (int j = 0; j < 8; j++) c[i][j] = 0ull;

    const int* idxb = g_idx + b * TCC * GG;

    for (int lt = 0; lt < LLAT; lt += 16) {       // 18 tiles; aligned to 144 split
        int lhi = (lt >= DD) ? 1 : 0;
        int d0  = lt - lhi * DD;
        #pragma unroll
        for (int r = 0; r < 8; r++) {             // 128f x 16l w2-tile
            int e = r * 256 + tid;
            int l = e & 15, f = e >> 4;
            as2[l * 129 + f] = dup2(w2[(size_t)(f0 + f) * LLAT + lt + l]);
        }
        #pragma unroll
        for (int r = 0; r < 16; r++) {            // 16l x 256t gathered q-tile
            int e = r * 256 + tid;
            int l = e & 15, t = e >> 4;
            int tt = t0 + t;
            int gq = ((tt & 1) << 1) | lhi;       // group = 2*frame_parity + l/144
            int ck = idxb[(tt >> 1) * GG + gq];
            qs[l * 258 + t] = cb[((size_t)(gq * KK + ck)) * DD + d0 + l];
        }
        __syncthreads();
        #pragma unroll
        for (int l = 0; l < 16; l++) {
            u64 av[8], bv[8];
            #pragma unroll
            for (int i = 0; i < 8; i++) av[i] = as2[l * 129 + i * 16 + ir];
            #pragma unroll
            for (int j = 0; j < 8; j++)
                bv[j] = *(const u64*)&qs[l * 258 + 2 * (j * 16 + kg)];
            #pragma unroll
            for (int i = 0; i < 8; i++)
                #pragma unroll
                for (int j = 0; j < 8; j++) fma2(c[i][j], av[i], bv[j]);
        }
        __syncthreads();
    }

    float* ob = out + ((size_t)b * FEAT + f0) * TT + t0;
    #pragma unroll
    for (int i = 0; i < 8; i++)
        #pragma unroll
        for (int j = 0; j < 8; j++)
            *(u64*)&ob[(size_t)(i * 16 + ir) * TT + 2 * (j * 16 + kg)] = c[i][j];
}

// ---------------------------------------------------------------------------
extern "C" void kernel_launch(void* const* d_in, const int* in_sizes, int n_in,
                              void* d_out, int out_size) {
    const float* x  = (const float*)d_in[0];
    const float* w1 = (const float*)d_in[1];
    const float* w2 = (const float*)d_in[2];
    const float* cb = (const float*)d_in[3];
    float* out = (float*)d_out;

    cudaFuncSetAttribute(dist_kernel,
                         cudaFuncAttributeMaxDynamicSharedMemorySize, DIST_SMEM);

    e2_kernel  <<<GG * KK / 8, 256>>>(cb);
    proj_kernel<<<dim3(TT / 128, 1, BB), 256>>>(x, w1);
    dist_kernel<<<dim3(BB * TCC / 128, GG), 256, DIST_SMEM>>>(cb);
    recon_kernel<<<dim3(TT / 256, FEAT / 128, BB), 256>>>(w2, cb, out);
}

// round 6
// speedup vs baseline: 1.1357x; 1.0460x over previous
#include <cuda_runtime.h>

#define BB   32
#define FEAT 512
#define TT   1024
#define LLAT 288
#define TCC  512
#define GG   4
#define KK   1024
#define DD   144

typedef unsigned long long u64;

// scratch (device globals: allocation-free rule)
__device__ __align__(256) float g_z[BB * TT * LLAT];   // z stored [b][t][l]
__device__ __align__(256) float g_e2[GG * KK];         // ||e||^2 per codeword
__device__ __align__(256) int   g_idx[BB * TCC * GG];  // argmin indices [b][tc][g]

__device__ __forceinline__ void fma2(u64 &c, u64 a, u64 b) {
    asm("fma.rn.f32x2 %0, %1, %2, %0;" : "+l"(c) : "l"(a), "l"(b));
}
__device__ __forceinline__ u64 dup2(float x) {
    u64 r; asm("mov.b64 %0, {%1, %1};" : "=l"(r) : "f"(x)); return r;
}
__device__ __forceinline__ float2 unpack2(u64 v) {
    float2 f; asm("mov.b64 {%0, %1}, %2;" : "=f"(f.x), "=f"(f.y) : "l"(v)); return f;
}
__device__ __forceinline__ unsigned smaddr(const void* p) {
    return (unsigned)__cvta_generic_to_shared(p);
}
__device__ __forceinline__ void cpasync4(unsigned s, const void* g) {
    asm volatile("cp.async.ca.shared.global [%0], [%1], 4;" :: "r"(s), "l"(g));
}
__device__ __forceinline__ void cpcommit() {
    asm volatile("cp.async.commit_group;");
}
__device__ __forceinline__ void cpwait0() {
    asm volatile("cp.async.wait_group 0;");
}

// ---------------------------------------------------------------------------
// Kernel 1: codeword squared norms  e2[g,k] = sum_d cb[g,k,d]^2
// ---------------------------------------------------------------------------
__global__ void e2_kernel(const float* __restrict__ cb) {
    int row  = blockIdx.x * 8 + (threadIdx.x >> 5);
    int lane = threadIdx.x & 31;
    const float* p = cb + (size_t)row * DD;
    float s = 0.f;
    #pragma unroll
    for (int d0 = 0; d0 < DD; d0 += 32) {
        int d = d0 + lane;
        if (d < DD) { float v = p[d]; s += v * v; }
    }
    #pragma unroll
    for (int o = 16; o; o >>= 1) s += __shfl_xor_sync(0xffffffffu, s, o);
    if (lane == 0) g_e2[row] = s;
}

// ---------------------------------------------------------------------------
// Kernel 2: projection  z[b][t][l] = sum_f x[b][f][t] * w1[l][f]
// Tile 128 t x 288 l, K-tile 16, double-buffered pipeline.
// ---------------------------------------------------------------------------
#define PROJ_SMEM (2*16*129*8 + 2*16*290*4)
#define PROJ_NT   (FEAT / 16)

__global__ __launch_bounds__(256, 1) void proj_kernel(
        const float* __restrict__ x, const float* __restrict__ w1) {
    extern __shared__ __align__(16) char smem[];
    u64*   xs2 = (u64*)smem;                       // [2][16][129] dup'd x
    float* ws  = (float*)(smem + 2*16*129*8);      // [2][16][290] w1

    const int b  = blockIdx.z;
    const int t0 = blockIdx.x * 128;
    const int tid = threadIdx.x;
    const int ir = tid & 15;        // t = i*16 + ir
    const int kg = tid >> 4;        // l pair p = j*16 + kg

    const float* xb = x + (size_t)b * FEAT * TT + t0;

    u64 c[8][9];
    #pragma unroll
    for (int i = 0; i < 8; i++)
        #pragma unroll
        for (int j = 0; j < 9; j++) c[i][j] = 0ull;

    float xr[8];
    // prologue: tile 0
    #pragma unroll
    for (int r = 0; r < 18; r++) {
        int e = r * 256 + tid;
        int l = e >> 4, k = e & 15;
        cpasync4(smaddr(&ws[k * 290 + l]), &w1[(size_t)l * FEAT + k]);
    }
    cpcommit();
    #pragma unroll
    for (int r = 0; r < 8; r++) {
        int e = r * 256 + tid;
        int k = e >> 7, t = e & 127;
        xr[r] = xb[(size_t)k * TT + t];
    }
    #pragma unroll
    for (int r = 0; r < 8; r++) {
        int e = r * 256 + tid;
        int k = e >> 7, t = e & 127;
        xs2[k * 129 + t] = dup2(xr[r]);
    }

    for (int n = 0; n < PROJ_NT; n++) {
        cpwait0();
        __syncthreads();
        const int n2 = n + 1;
        if (n2 < PROJ_NT) {
            const int kt2 = n2 * 16;
            float* wd = ws + (n2 & 1) * (16 * 290);
            #pragma unroll
            for (int r = 0; r < 18; r++) {
                int e = r * 256 + tid;
                int l = e >> 4, k = e & 15;
                cpasync4(smaddr(&wd[k * 290 + l]), &w1[(size_t)l * FEAT + kt2 + k]);
            }
            #pragma unroll
            for (int r = 0; r < 8; r++) {
                int e = r * 256 + tid;
                int k = e >> 7, t = e & 127;
                xr[r] = xb[(size_t)(kt2 + k) * TT + t];
            }
        }
        cpcommit();

        const u64*   xc = xs2 + (n & 1) * (16 * 129);
        const float* wc = ws  + (n & 1) * (16 * 290);
        #pragma unroll
        for (int k = 0; k < 16; k++) {
            u64 av[8], bv[9];
            #pragma unroll
            for (int i = 0; i < 8; i++) av[i] = xc[k * 129 + i * 16 + ir];
            #pragma unroll
            for (int j = 0; j < 9; j++)
                bv[j] = *(const u64*)&wc[k * 290 + 2 * (j * 16 + kg)];
            #pragma unroll
            for (int i = 0; i < 8; i++)
                #pragma unroll
                for (int j = 0; j < 9; j++) fma2(c[i][j], av[i], bv[j]);
        }
        if (n2 < PROJ_NT) {
            u64* xd = xs2 + (n2 & 1) * (16 * 129);
            #pragma unroll
            for (int r = 0; r < 8; r++) {
                int e = r * 256 + tid;
                int k = e >> 7, t = e & 127;
                xd[k * 129 + t] = dup2(xr[r]);
            }
        }
    }

    float* zb = g_z + (size_t)b * TT * LLAT;
    #pragma unroll
    for (int i = 0; i < 8; i++) {
        int t = t0 + i * 16 + ir;
        #pragma unroll
        for (int j = 0; j < 9; j++)
            *(u64*)&zb[(size_t)t * LLAT + 2 * (j * 16 + kg)] = c[i][j];
    }
}

// ---------------------------------------------------------------------------
// Kernel 3: distance + argmin per (b,tc,g).
// Block: 128 rows x k-tile 256.  v resident (dup'd); cb double-buffered cp.async.
// score = e2[k] - 2*<v,e_k>   (||v||^2 row-constant -> dropped).
// ---------------------------------------------------------------------------
#define DIST_SMEM (144*129*8 + 2*16*258*4 + 1024*4 + 128*16*4 + 128*16*4)
#define DIST_NT   (4 * 9)   // 4 kt-tiles x 9 dt-tiles

__global__ __launch_bounds__(256, 1) void dist_kernel(const float* __restrict__ cb) {
    extern __shared__ __align__(16) char smem[];
    u64*   vs2  = (u64*)smem;                        // [144][129] dup'd v [d][r]
    float* cbs  = (float*)(smem + 144 * 129 * 8);    // [2][16][258]
    float* e2s  = cbs + 2 * 16 * 258;                // [1024]
    float* rmin = e2s + 1024;                        // [128][16]
    int*   rkid = (int*)(rmin + 128 * 16);           // [128][16]

    const int g  = blockIdx.y;
    const int r0 = blockIdx.x * 128;
    const int tid = threadIdx.x;
    const int ir = tid & 15;      // row r = i*16 + ir
    const int kg = tid >> 4;      // k pair p = j*16 + kg

    const float* cbg = cb + (size_t)g * KK * DD;

    // prologue: prefetch tile 0 (kt=0, dt=0)
    #pragma unroll
    for (int r = 0; r < 16; r++) {
        int e = r * 256 + tid;
        int k = e >> 4, d = e & 15;
        cpasync4(smaddr(&cbs[d * 258 + k]), &cbg[(size_t)k * DD + d]);
    }
    cpcommit();

    for (int e = tid; e < KK; e += 256) e2s[e] = g_e2[g * KK + e];

    const int lbase = (g & 1) * DD;
    const int pofs  = g >> 1;
    for (int e = tid; e < 128 * DD; e += 256) {
        int r = e / DD, d = e - r * DD;
        int rg = r0 + r;
        int b = rg >> 9, tc = rg & 511;
        vs2[d * 129 + r] =
            dup2(g_z[(size_t)(b * TT + 2 * tc + pofs) * LLAT + lbase + d]);
    }

    float minv[8]; int mink[8];
    #pragma unroll
    for (int i = 0; i < 8; i++) { minv[i] = 3.4e38f; mink[i] = 0; }

    int n = 0;
    for (int kt = 0; kt < KK; kt += 256) {
        u64 c[8][8];
        #pragma unroll
        for (int i = 0; i < 8; i++)
            #pragma unroll
            for (int j = 0; j < 8; j++) c[i][j] = 0ull;

        for (int dt = 0; dt < DD; dt += 16, n++) {
            cpwait0();
            __syncthreads();
            const int n2 = n + 1;
            if (n2 < DIST_NT) {
                const int kt2 = (n2 / 9) * 256;
                const int dt2 = (n2 % 9) * 16;
                float* dst = cbs + (n2 & 1) * (16 * 258);
                #pragma unroll
                for (int r = 0; r < 16; r++) {
                    int e = r * 256 + tid;
                    int k = e >> 4, d = e & 15;
                    cpasync4(smaddr(&dst[d * 258 + k]),
                             &cbg[(size_t)(kt2 + k) * DD + dt2 + d]);
                }
            }
            cpcommit();

            const float* cur = cbs + (n & 1) * (16 * 258);
            #pragma unroll
            for (int dd = 0; dd < 16; dd++) {
                u64 av[8], bv[8];
                #pragma unroll
                for (int i = 0; i < 8; i++)
                    av[i] = vs2[(dt + dd) * 129 + i * 16 + ir];
                #pragma unroll
                for (int j = 0; j < 8; j++)
                    bv[j] = *(const u64*)&cur[dd * 258 + 2 * (j * 16 + kg)];
                #pragma unroll
                for (int i = 0; i < 8; i++)
                    #pragma unroll
                    for (int j = 0; j < 8; j++) fma2(c[i][j], av[i], bv[j]);
            }
        }
        // fold this col-tile into running argmin (k ascending within thread)
        #pragma unroll
        for (int j = 0; j < 8; j++) {
            int ke = kt + 2 * (j * 16 + kg);
            float e0 = e2s[ke], e1 = e2s[ke + 1];
            #pragma unroll
            for (int i = 0; i < 8; i++) {
                float2 f = unpack2(c[i][j]);
                float s0 = e0 - 2.f * f.x;
                float s1 = e1 - 2.f * f.y;
                if (s0 < minv[i]) { minv[i] = s0; mink[i] = ke; }
                if (s1 < minv[i]) { minv[i] = s1; mink[i] = ke + 1; }
            }
        }
    }

    #pragma unroll
    for (int i = 0; i < 8; i++) {
        int r = i * 16 + ir;
        rmin[r * 16 + kg] = minv[i];
        rkid[r * 16 + kg] = mink[i];
    }
    __syncthreads();
    if (tid < 128) {  // reduce 16 partials per row; tie-break to lowest k
        float bvv = rmin[tid * 16]; int bk = rkid[tid * 16];
        #pragma unroll
        for (int q = 1; q < 16; q++) {
            float v = rmin[tid * 16 + q]; int k = rkid[tid * 16 + q];
            if (v < bvv || (v == bvv && k < bk)) { bvv = v; bk = k; }
        }
        g_idx[(r0 + tid) * GG + g] = bk;
    }
}

// ---------------------------------------------------------------------------
// Kernel 4: reconstruction  out[b][f][t] = sum_l w2[f][l] * q[b][t][l]
// Tile 128 f x 256 t, K-tile 16 over l, double-buffered pipeline.
// Codebook indices pre-staged in SMEM; q gathered via cp.async.
// ---------------------------------------------------------------------------
#define RECON_SMEM (2*16*129*8 + 2*16*258*4 + 512*4)
#define RECON_NT   (LLAT / 16)

__global__ __launch_bounds__(256, 1) void recon_kernel(
        const float* __restrict__ w2, const float* __restrict__ cb,
        float* __restrict__ out) {
    extern __shared__ __align__(16) char smem[];
    u64*   as2  = (u64*)smem;                      // [2][16][129] dup'd w2
    float* qs   = (float*)(smem + 2*16*129*8);     // [2][16][258] gathered q
    int*   idxs = (int*)(smem + 2*16*129*8 + 2*16*258*4);  // [128][4]

    const int b  = blockIdx.z;
    const int t0 = blockIdx.x * 256;
    const int f0 = blockIdx.y * 128;
    const int tid = threadIdx.x;
    const int ir = tid & 15;      // f = i*16 + ir
    const int kg = tid >> 4;      // t pair p = j*16 + kg

    const int* idxb = g_idx + b * TCC * GG + (t0 >> 1) * GG;

    // stage this block's 512 codebook indices
    for (int e = tid; e < 512; e += 256) idxs[e] = idxb[e];
    __syncthreads();

    u64 c[8][8];
    #pragma unroll
    for (int i = 0; i < 8; i++)
        #pragma unroll
        for (int j = 0; j < 8; j++) c[i][j] = 0ull;

    float wr[8];
    // prologue: tile 0 (lt=0 -> lhi=0, d0=0)
    #pragma unroll
    for (int r = 0; r < 16; r++) {
        int e = r * 256 + tid;
        int l = e & 15, t = e >> 4;
        int gq = (t & 1) << 1;
        int ck = idxs[(t >> 1) * 4 + gq];
        cpasync4(smaddr(&qs[l * 258 + t]),
                 &cb[((size_t)(gq * KK + ck)) * DD + l]);
    }
    cpcommit();
    #pragma unroll
    for (int r = 0; r < 8; r++) {
        int e = r * 256 + tid;
        int l = e & 15, f = e >> 4;
        wr[r] = w2[(size_t)(f0 + f) * LLAT + l];
    }
    #pragma unroll
    for (int r = 0; r < 8; r++) {
        int e = r * 256 + tid;
        int l = e & 15, f = e >> 4;
        as2[l * 129 + f] = dup2(wr[r]);
    }

    for (int n = 0; n < RECON_NT; n++) {
        cpwait0();
        __syncthreads();
        const int n2 = n + 1;
        if (n2 < RECON_NT) {
            const int lt2  = n2 * 16;
            const int lhi2 = (lt2 >= DD) ? 1 : 0;
            const int d02  = lt2 - lhi2 * DD;
            float* qd = qs + (n2 & 1) * (16 * 258);
            #pragma unroll
            for (int r = 0; r < 16; r++) {
                int e = r * 256 + tid;
                int l = e & 15, t = e >> 4;
                int gq = ((t & 1) << 1) | lhi2;
                int ck = idxs[(t >> 1) * 4 + gq];
                cpasync4(smaddr(&qd[l * 258 + t]),
                         &cb[((size_t)(gq * KK + ck)) * DD + d02 + l]);
            }
            #pragma unroll
            for (int r = 0; r < 8; r++) {
                int e = r * 256 + tid;
                int l = e & 15, f = e >> 4;
                wr[r] = w2[(size_t)(f0 + f) * LLAT + lt2 + l];
            }
        }
        cpcommit();

        const u64*   ac = as2 + (n & 1) * (16 * 129);
        const float* qc = qs  + (n & 1) * (16 * 258);
        #pragma unroll
        for (int l = 0; l < 16; l++) {
            u64 av[8], bv[8];
            #pragma unroll
            for (int i = 0; i < 8; i++) av[i] = ac[l * 129 + i * 16 + ir];
            #pragma unroll
            for (int j = 0; j < 8; j++)
                bv[j] = *(const u64*)&qc[l * 258 + 2 * (j * 16 + kg)];
            #pragma unroll
            for (int i = 0; i < 8; i++)
                #pragma unroll
                for (int j = 0; j < 8; j++) fma2(c[i][j], av[i], bv[j]);
        }
        if (n2 < RECON_NT) {
            u64* ad = as2 + (n2 & 1) * (16 * 129);
            #pragma unroll
            for (int r = 0; r < 8; r++) {
                int e = r * 256 + tid;
                int l = e & 15, f = e >> 4;
                ad[l * 129 + f] = dup2(wr[r]);
            }
        }
    }

    float* ob = out + ((size_t)b * FEAT + f0) * TT + t0;
    #pragma unroll
    for (int i = 0; i < 8; i++)
        #pragma unroll
        for (int j = 0; j < 8; j++)
            *(u64*)&ob[(size_t)(i * 16 + ir) * TT + 2 * (j * 16 + kg)] = c[i][j];
}

// ---------------------------------------------------------------------------
extern "C" void kernel_launch(void* const* d_in, const int* in_sizes, int n_in,
                              void* d_out, int out_size) {
    const float* x  = (const float*)d_in[0];
    const float* w1 = (const float*)d_in[1];
    const float* w2 = (const float*)d_in[2];
    const float* cb = (const float*)d_in[3];
    float* out = (float*)d_out;

    cudaFuncSetAttribute(proj_kernel,
                         cudaFuncAttributeMaxDynamicSharedMemorySize, PROJ_SMEM);
    cudaFuncSetAttribute(dist_kernel,
                         cudaFuncAttributeMaxDynamicSharedMemorySize, DIST_SMEM);
    cudaFuncSetAttribute(recon_kernel,
                         cudaFuncAttributeMaxDynamicSharedMemorySize, RECON_SMEM);

    e2_kernel  <<<GG * KK / 8, 256>>>(cb);
    proj_kernel<<<dim3(TT / 128, 1, BB), 256, PROJ_SMEM>>>(x, w1);
    dist_kernel<<<dim3(BB * TCC / 128, GG), 256, DIST_SMEM>>>(cb);
    recon_kernel<<<dim3(TT / 256, FEAT / 128, BB), 256, RECON_SMEM>>>(w2, cb, out);
}

// round 12
// speedup vs baseline: 1.2386x; 1.0907x over previous
#include <cuda_runtime.h>
#include <cuda_bf16.h>
#include <cstdint>

#define BB   32
#define FEAT 512
#define TT   1024
#define LLAT 288
#define TCC  512
#define GG   4
#define KK   1024
#define DD   144

typedef unsigned long long u64;

// scratch (device globals: allocation-free rule)
__device__ __align__(256) float g_z[BB * TT * LLAT];   // z stored [b][t][l]
__device__ __align__(256) float g_e2[GG * KK];         // ||e||^2 per codeword
__device__ __align__(256) int   g_idx[BB * TCC * GG];  // argmin indices [b][tc][g]

// ---------------------------------------------------------------------------
// helpers
// ---------------------------------------------------------------------------
__device__ __forceinline__ void fma2(u64 &c, u64 a, u64 b) {
    asm("fma.rn.f32x2 %0, %1, %2, %0;" : "+l"(c) : "l"(a), "l"(b));
}
__device__ __forceinline__ u64 dup2(float x) {
    u64 r; asm("mov.b64 %0, {%1, %1};" : "=l"(r) : "f"(x)); return r;
}
__device__ __forceinline__ float2 unpack2(u64 v) {
    float2 f; asm("mov.b64 {%0, %1}, %2;" : "=f"(f.x), "=f"(f.y) : "l"(v)); return f;
}
__device__ __forceinline__ unsigned smaddr(const void* p) {
    return (unsigned)__cvta_generic_to_shared(p);
}
__device__ __forceinline__ void cpasync4(unsigned s, const void* g) {
    asm volatile("cp.async.ca.shared.global [%0], [%1], 4;" :: "r"(s), "l"(g));
}
__device__ __forceinline__ void cpcommit() { asm volatile("cp.async.commit_group;"); }
__device__ __forceinline__ void cpwait0()  { asm volatile("cp.async.wait_group 0;"); }

// warp-level bf16 tensor-core mma (sm_80+ feature, works on sm_100 target)
__device__ __forceinline__ void mma16816(float* c, const uint32_t* a,
                                         const uint32_t* b) {
    asm volatile(
        "mma.sync.aligned.m16n8k16.row.col.f32.bf16.bf16.f32 "
        "{%0,%1,%2,%3}, {%4,%5,%6,%7}, {%8,%9}, {%0,%1,%2,%3};"
        : "+f"(c[0]), "+f"(c[1]), "+f"(c[2]), "+f"(c[3])
        : "r"(a[0]), "r"(a[1]), "r"(a[2]), "r"(a[3]), "r"(b[0]), "r"(b[1]));
}

// fp32 -> bf16 splits
__device__ __forceinline__ void split3(float v, __nv_bfloat16 &h,
                                       __nv_bfloat16 &m, __nv_bfloat16 &l) {
    h = __float2bfloat16(v); float r = v - __bfloat162float(h);
    m = __float2bfloat16(r); r = r - __bfloat162float(m);
    l = __float2bfloat16(r);
}
__device__ __forceinline__ void split2(float v, __nv_bfloat16 &h, __nv_bfloat16 &l) {
    h = __float2bfloat16(v); float r = v - __bfloat162float(h);
    l = __float2bfloat16(r);
}
__device__ __forceinline__ uint32_t pack_bf2(__nv_bfloat16 a, __nv_bfloat16 b) {
    __nv_bfloat162 p; p.x = a; p.y = b;
    return *reinterpret_cast<uint32_t*>(&p);
}

// ---------------------------------------------------------------------------
// Kernel 1: codeword squared norms  e2[g,k] = sum_d cb[g,k,d]^2
// ---------------------------------------------------------------------------
__global__ void e2_kernel(const float* __restrict__ cb) {
    int row  = blockIdx.x * 8 + (threadIdx.x >> 5);
    int lane = threadIdx.x & 31;
    const float* p = cb + (size_t)row * DD;
    float s = 0.f;
    #pragma unroll
    for (int d0 = 0; d0 < DD; d0 += 32) {
        int d = d0 + lane;
        if (d < DD) { float v = p[d]; s += v * v; }
    }
    #pragma unroll
    for (int o = 16; o; o >>= 1) s += __shfl_xor_sync(0xffffffffu, s, o);
    if (lane == 0) g_e2[row] = s;
}

// ---------------------------------------------------------------------------
// Kernel 2 (mma.sync): proj  z[b][t][l] = sum_f x[b][f][t] * w1[l][f]
// Block 128 t x 288 l, K=512 in chunks of 32 (2 k16-steps).
// bf16 3-way split, 6 cross products. Warp tile 32t x 144l.
// A smem [3 spl][2 ks][128 m(t)][16 k] bf16; B smem [3][2][288 n(l)][16 k].
// ---------------------------------------------------------------------------
#define PROJ_ASZ (3 * 2 * 128 * 16)           // elems
#define PROJ_BSZ (3 * 2 * 288 * 16)
#define PROJ_SMEM ((PROJ_ASZ + PROJ_BSZ) * 2) // bytes = 79872

__global__ __launch_bounds__(256, 1) void proj_mma_kernel(
        const float* __restrict__ x, const float* __restrict__ w1) {
    extern __shared__ __align__(16) char smem[];
    __nv_bfloat16* Asm = (__nv_bfloat16*)smem;
    __nv_bfloat16* Bsm = (__nv_bfloat16*)(smem + PROJ_ASZ * 2);

    const int tid  = threadIdx.x;
    const int wid  = tid >> 5;
    const int lane = tid & 31;
    const int gr   = lane >> 2;          // group row 0..7
    const int gc   = (lane & 3) * 2;     // group col (even)
    const int b    = blockIdx.y;
    const int t0   = blockIdx.x * 128;
    const int m0w  = (wid & 3) * 32;     // warp t offset
    const int n0w  = (wid >> 2) * 144;   // warp l offset

    const float* xb = x + (size_t)b * FEAT * TT + t0;

    float acc[2][18][4];
    #pragma unroll
    for (int mt = 0; mt < 2; mt++)
        #pragma unroll
        for (int nt = 0; nt < 18; nt++)
            #pragma unroll
            for (int r = 0; r < 4; r++) acc[mt][nt][r] = 0.f;

    for (int c = 0; c < 16; c++) {
        const int f0c = c * 32;
        __syncthreads();   // previous compute done before overwrite
        // A = x^T [128 t][32 f] -> bf16 x3
        #pragma unroll
        for (int i = 0; i < 16; i++) {
            int e = i * 256 + tid;
            int t = e & 127, kk = e >> 7;          // kk 0..31
            float v = xb[(size_t)(f0c + kk) * TT + t];
            __nv_bfloat16 h, m, l; split3(v, h, m, l);
            int base = ((kk >> 4) * 128 + t) * 16 + (kk & 15);
            Asm[base]                = h;
            Asm[base + 2 * 128 * 16] = m;
            Asm[base + 4 * 128 * 16] = l;
        }
        // B = w1 [288 l][32 f] -> bf16 x3
        #pragma unroll
        for (int i = 0; i < 18; i++) {
            int e = i * 256 + tid;
            int l = e >> 4, fp = e & 15;           // k pair = 2*fp
            float2 v = *(const float2*)&w1[(size_t)l * FEAT + f0c + 2 * fp];
            __nv_bfloat16 h0, m0, l0, h1, m1, l1;
            split3(v.x, h0, m0, l0); split3(v.y, h1, m1, l1);
            int base = ((fp >> 3) * 288 + l) * 16 + ((2 * fp) & 15);
            *(uint32_t*)&Bsm[base]                = pack_bf2(h0, h1);
            *(uint32_t*)&Bsm[base + 2 * 288 * 16] = pack_bf2(m0, m1);
            *(uint32_t*)&Bsm[base + 4 * 288 * 16] = pack_bf2(l0, l1);
        }
        __syncthreads();

        const int pa[6] = {0, 0, 1, 0, 2, 1};
        const int pb[6] = {0, 1, 0, 2, 0, 1};
        #pragma unroll
        for (int ks = 0; ks < 2; ks++) {
            #pragma unroll
            for (int q = 0; q < 6; q++) {
                const __nv_bfloat16* Ab = Asm + (pa[q] * 2 + ks) * (128 * 16);
                const __nv_bfloat16* Bb = Bsm + (pb[q] * 2 + ks) * (288 * 16);
                uint32_t af[2][4];
                #pragma unroll
                for (int mt = 0; mt < 2; mt++)
                    #pragma unroll
                    for (int r = 0; r < 4; r++) {
                        int row = m0w + mt * 16 + gr + (r & 1) * 8;
                        int kcol = gc + (r >> 1) * 8;
                        af[mt][r] = *(const uint32_t*)&Ab[row * 16 + kcol];
                    }
                #pragma unroll
                for (int nt = 0; nt < 18; nt++) {
                    uint32_t bf[2];
                    int nn = n0w + nt * 8 + gr;
                    bf[0] = *(const uint32_t*)&Bb[nn * 16 + gc];
                    bf[1] = *(const uint32_t*)&Bb[nn * 16 + gc + 8];
                    mma16816(acc[0][nt], af[0], bf);
                    mma16816(acc[1][nt], af[1], bf);
                }
            }
        }
    }

    float* zb = g_z + ((size_t)b * TT + t0) * LLAT;
    #pragma unroll
    for (int mt = 0; mt < 2; mt++) {
        #pragma unroll
        for (int nt = 0; nt < 18; nt++) {
            int tr = m0w + mt * 16 + gr;
            int lc = n0w + nt * 8 + gc;
            float2 v0 = make_float2(acc[mt][nt][0], acc[mt][nt][1]);
            float2 v1 = make_float2(acc[mt][nt][2], acc[mt][nt][3]);
            *(float2*)&zb[(size_t)tr * LLAT + lc]       = v0;
            *(float2*)&zb[(size_t)(tr + 8) * LLAT + lc] = v1;
        }
    }
}

// ---------------------------------------------------------------------------
// Kernel 3: distance + argmin per (b,tc,g)  (proven fp32 path, unchanged)
// ---------------------------------------------------------------------------
#define DIST_SMEM (144*129*8 + 2*16*258*4 + 1024*4 + 128*16*4 + 128*16*4)
#define DIST_NT   (4 * 9)

__global__ __launch_bounds__(256, 1) void dist_kernel(const float* __restrict__ cb) {
    extern __shared__ __align__(16) char smem[];
    u64*   vs2  = (u64*)smem;                        // [144][129] dup'd v [d][r]
    float* cbs  = (float*)(smem + 144 * 129 * 8);    // [2][16][258]
    float* e2s  = cbs + 2 * 16 * 258;                // [1024]
    float* rmin = e2s + 1024;                        // [128][16]
    int*   rkid = (int*)(rmin + 128 * 16);           // [128][16]

    const int g  = blockIdx.y;
    const int r0 = blockIdx.x * 128;
    const int tid = threadIdx.x;
    const int ir = tid & 15;
    const int kg = tid >> 4;

    const float* cbg = cb + (size_t)g * KK * DD;

    #pragma unroll
    for (int r = 0; r < 16; r++) {
        int e = r * 256 + tid;
        int k = e >> 4, d = e & 15;
        cpasync4(smaddr(&cbs[d * 258 + k]), &cbg[(size_t)k * DD + d]);
    }
    cpcommit();

    for (int e = tid; e < KK; e += 256) e2s[e] = g_e2[g * KK + e];

    const int lbase = (g & 1) * DD;
    const int pofs  = g >> 1;
    for (int e = tid; e < 128 * DD; e += 256) {
        int r = e / DD, d = e - r * DD;
        int rg = r0 + r;
        int b = rg >> 9, tc = rg & 511;
        vs2[d * 129 + r] =
            dup2(g_z[(size_t)(b * TT + 2 * tc + pofs) * LLAT + lbase + d]);
    }

    float minv[8]; int mink[8];
    #pragma unroll
    for (int i = 0; i < 8; i++) { minv[i] = 3.4e38f; mink[i] = 0; }

    int n = 0;
    for (int kt = 0; kt < KK; kt += 256) {
        u64 c[8][8];
        #pragma unroll
        for (int i = 0; i < 8; i++)
            #pragma unroll
            for (int j = 0; j < 8; j++) c[i][j] = 0ull;

        for (int dt = 0; dt < DD; dt += 16, n++) {
            cpwait0();
            __syncthreads();
            const int n2 = n + 1;
            if (n2 < DIST_NT) {
                const int kt2 = (n2 / 9) * 256;
                const int dt2 = (n2 % 9) * 16;
                float* dst = cbs + (n2 & 1) * (16 * 258);
                #pragma unroll
                for (int r = 0; r < 16; r++) {
                    int e = r * 256 + tid;
                    int k = e >> 4, d = e & 15;
                    cpasync4(smaddr(&dst[d * 258 + k]),
                             &cbg[(size_t)(kt2 + k) * DD + dt2 + d]);
                }
            }
            cpcommit();

            const float* cur = cbs + (n & 1) * (16 * 258);
            #pragma unroll
            for (int dd = 0; dd < 16; dd++) {
                u64 av[8], bv[8];
                #pragma unroll
                for (int i = 0; i < 8; i++)
                    av[i] = vs2[(dt + dd) * 129 + i * 16 + ir];
                #pragma unroll
                for (int j = 0; j < 8; j++)
                    bv[j] = *(const u64*)&cur[dd * 258 + 2 * (j * 16 + kg)];
                #pragma unroll
                for (int i = 0; i < 8; i++)
                    #pragma unroll
                    for (int j = 0; j < 8; j++) fma2(c[i][j], av[i], bv[j]);
            }
        }
        #pragma unroll
        for (int j = 0; j < 8; j++) {
            int ke = kt + 2 * (j * 16 + kg);
            float e0 = e2s[ke], e1 = e2s[ke + 1];
            #pragma unroll
            for (int i = 0; i < 8; i++) {
                float2 f = unpack2(c[i][j]);
                float s0 = e0 - 2.f * f.x;
                float s1 = e1 - 2.f * f.y;
                if (s0 < minv[i]) { minv[i] = s0; mink[i] = ke; }
                if (s1 < minv[i]) { minv[i] = s1; mink[i] = ke + 1; }
            }
        }
    }

    #pragma unroll
    for (int i = 0; i < 8; i++) {
        int r = i * 16 + ir;
        rmin[r * 16 + kg] = minv[i];
        rkid[r * 16 + kg] = mink[i];
    }
    __syncthreads();
    if (tid < 128) {
        float bvv = rmin[tid * 16]; int bk = rkid[tid * 16];
        #pragma unroll
        for (int q = 1; q < 16; q++) {
            float v = rmin[tid * 16 + q]; int k = rkid[tid * 16 + q];
            if (v < bvv || (v == bvv && k < bk)) { bvv = v; bk = k; }
        }
        g_idx[(r0 + tid) * GG + g] = bk;
    }
}

// ---------------------------------------------------------------------------
// Kernel 4 (mma.sync): recon  out[b][f][t] = sum_l w2[f][l] * q[b][t][l]
// Block 128 f x 256 t, K=288 in chunks of 48 (3 k16-steps, 6 chunks).
// bf16 2-way split, 3 products. Warp tile 32f x 128t.
// A smem [2][3][128 m(f)][16 k]; B smem [2][3][256 n(t)][16 k]; idx [512].
// ---------------------------------------------------------------------------
#define REC_ASZ (2 * 3 * 128 * 16)            // elems
#define REC_BSZ (2 * 3 * 256 * 16)
#define REC_IDX_OFF ((REC_ASZ + REC_BSZ) * 2) // 73728 bytes
#define RECON_SMEM (REC_IDX_OFF + 512 * 4)

__global__ __launch_bounds__(256, 1) void recon_mma_kernel(
        const float* __restrict__ w2, const float* __restrict__ cb,
        float* __restrict__ out) {
    extern __shared__ __align__(16) char smem[];
    __nv_bfloat16* Asm = (__nv_bfloat16*)smem;
    __nv_bfloat16* Bsm = (__nv_bfloat16*)(smem + REC_ASZ * 2);
    int* idxs = (int*)(smem + REC_IDX_OFF);

    const int tid  = threadIdx.x;
    const int wid  = tid >> 5;
    const int lane = tid & 31;
    const int gr   = lane >> 2;
    const int gc   = (lane & 3) * 2;
    const int b    = blockIdx.z;
    const int t0   = blockIdx.x * 256;
    const int f0   = blockIdx.y * 128;
    const int m0w  = (wid & 3) * 32;     // warp f offset
    const int n0w  = (wid >> 2) * 128;   // warp t offset

    for (int e = tid; e < 512; e += 256)
        idxs[e] = g_idx[b * TCC * GG + (t0 >> 1) * GG + e];

    float acc[2][16][4];
    #pragma unroll
    for (int mt = 0; mt < 2; mt++)
        #pragma unroll
        for (int nt = 0; nt < 16; nt++)
            #pragma unroll
            for (int r = 0; r < 4; r++) acc[mt][nt][r] = 0.f;

    for (int c = 0; c < 6; c++) {
        const int l0c = c * 48;
        const int lhi = (c >= 3) ? 1 : 0;
        const int d0  = l0c - lhi * DD;
        __syncthreads();
        // A = w2 [128 f][48 l] bf16 x2
        #pragma unroll
        for (int i = 0; i < 12; i++) {
            int e = i * 256 + tid;
            int f = e / 24, lp = e % 24;
            float2 v = *(const float2*)&w2[(size_t)(f0 + f) * LLAT + l0c + 2 * lp];
            __nv_bfloat16 h0, q0, h1, q1;
            split2(v.x, h0, q0); split2(v.y, h1, q1);
            int base = ((lp >> 3) * 128 + f) * 16 + ((2 * lp) & 15);
            *(uint32_t*)&Asm[base]                = pack_bf2(h0, h1);
            *(uint32_t*)&Asm[base + 3 * 128 * 16] = pack_bf2(q0, q1);
        }
        // B = gathered q [256 t][48 l] bf16 x2
        #pragma unroll
        for (int i = 0; i < 24; i++) {
            int e = i * 256 + tid;
            int t = e / 24, lp = e % 24;
            int gq = ((t & 1) << 1) | lhi;
            int ck = idxs[(t >> 1) * 4 + gq];
            float2 v = *(const float2*)&cb[((size_t)(gq * KK + ck)) * DD + d0 + 2 * lp];
            __nv_bfloat16 h0, q0, h1, q1;
            split2(v.x, h0, q0); split2(v.y, h1, q1);
            int base = ((lp >> 3) * 256 + t) * 16 + ((2 * lp) & 15);
            *(uint32_t*)&Bsm[base]                = pack_bf2(h0, h1);
            *(uint32_t*)&Bsm[base + 3 * 256 * 16] = pack_bf2(q0, q1);
        }
        __syncthreads();

        const int pa[3] = {0, 1, 0};
        const int pb[3] = {0, 0, 1};
        #pragma unroll
        for (int ks = 0; ks < 3; ks++) {
            #pragma unroll
            for (int q = 0; q < 3; q++) {
                const __nv_bfloat16* Ab = Asm + (pa[q] * 3 + ks) * (128 * 16);
                const __nv_bfloat16* Bb = Bsm + (pb[q] * 3 + ks) * (256 * 16);
                uint32_t af[2][4];
                #pragma unroll
                for (int mt = 0; mt < 2; mt++)
                    #pragma unroll
                    for (int r = 0; r < 4; r++) {
                        int row = m0w + mt * 16 + gr + (r & 1) * 8;
                        int kcol = gc + (r >> 1) * 8;
                        af[mt][r] = *(const uint32_t*)&Ab[row * 16 + kcol];
                    }
                #pragma unroll
                for (int nt = 0; nt < 16; nt++) {
                    uint32_t bf[2];
                    int nn = n0w + nt * 8 + gr;
                    bf[0] = *(const uint32_t*)&Bb[nn * 16 + gc];
                    bf[1] = *(const uint32_t*)&Bb[nn * 16 + gc + 8];
                    mma16816(acc[0][nt], af[0], bf);
                    mma16816(acc[1][nt], af[1], bf);
                }
            }
        }
    }

    float* ob = out + ((size_t)b * FEAT + f0) * TT + t0;
    #pragma unroll
    for (int mt = 0; mt < 2; mt++) {
        #pragma unroll
        for (int nt = 0; nt < 16; nt++) {
            int fr = m0w + mt * 16 + gr;
            int tc = n0w + nt * 8 + gc;
            float2 v0 = make_float2(acc[mt][nt][0], acc[mt][nt][1]);
            float2 v1 = make_float2(acc[mt][nt][2], acc[mt][nt][3]);
            *(float2*)&ob[(size_t)fr * TT + tc]       = v0;
            *(float2*)&ob[(size_t)(fr + 8) * TT + tc] = v1;
        }
    }
}

// ---------------------------------------------------------------------------
extern "C" void kernel_launch(void* const* d_in, const int* in_sizes, int n_in,
                              void* d_out, int out_size) {
    const float* x  = (const float*)d_in[0];
    const float* w1 = (const float*)d_in[1];
    const float* w2 = (const float*)d_in[2];
    const float* cb = (const float*)d_in[3];
    float* out = (float*)d_out;

    cudaFuncSetAttribute(proj_mma_kernel,
                         cudaFuncAttributeMaxDynamicSharedMemorySize, PROJ_SMEM);
    cudaFuncSetAttribute(dist_kernel,
                         cudaFuncAttributeMaxDynamicSharedMemorySize, DIST_SMEM);
    cudaFuncSetAttribute(recon_mma_kernel,
                         cudaFuncAttributeMaxDynamicSharedMemorySize, RECON_SMEM);

    e2_kernel<<<GG * KK / 8, 256>>>(cb);
    proj_mma_kernel<<<dim3(TT / 128, BB), 256, PROJ_SMEM>>>(x, w1);
    dist_kernel<<<dim3(BB * TCC / 128, GG), 256, DIST_SMEM>>>(cb);
    recon_mma_kernel<<<dim3(TT / 256, FEAT / 128, BB), 256, RECON_SMEM>>>(w2, cb, out);
}